// round 15
// baseline (speedup 1.0000x reference)
#include <cuda_runtime.h>
#include <math.h>
#include <stddef.h>

// ======================= packed fp32x2 helpers (Blackwell FFMA2) =============
__device__ __forceinline__ unsigned long long pack2(float lo, float hi) {
    unsigned long long r;
    asm("mov.b64 %0, {%1, %2};" : "=l"(r) : "f"(lo), "f"(hi));
    return r;
}
__device__ __forceinline__ unsigned long long dup2(float v) {
    unsigned long long r;
    asm("mov.b64 %0, {%1, %1};" : "=l"(r) : "f"(v));
    return r;
}
__device__ __forceinline__ void fma2(unsigned long long& acc, unsigned long long a,
                                     unsigned long long b) {
    asm("fma.rn.f32x2 %0, %1, %2, %3;" : "=l"(acc) : "l"(a), "l"(b), "l"(acc));
}
__device__ __forceinline__ float2 unpack2(unsigned long long v) {
    float lo, hi;
    asm("mov.b64 {%0, %1}, %2;" : "=f"(lo), "=f"(hi) : "l"(v));
    return make_float2(lo, hi);
}

// ======================= scratch arena (no allocations) =======================
static const size_t SZ_E1  = 64ull*256*256;
static const size_t SZ_P1  = 64ull*128*128;
static const size_t SZ_E2  = 128ull*128*128;
static const size_t SZ_P2  = 128ull*64*64;
static const size_t SZ_SEQ = 4096ull*256;
static const size_t SZ_LN  = 4096ull*256;
static const size_t SZ_QK  = 4096ull*256;
static const size_t SZ_V   = 4096ull*256;
static const size_t SZ_KINV= 4ull*4096;
static const size_t SZ_AO  = 4096ull*256;
static const size_t SZ_FFH = 4096ull*1024;
static const size_t SZ_BM  = 256ull*4096;
static const size_t SZ_UP1 = 128ull*128*128;
static const size_t SZ_D1  = 128ull*128*128;
static const size_t SZ_UP2 = 64ull*256*256;
static const size_t SZ_D2  = 64ull*256*256;

static const size_t OFF_E1  = 0;
static const size_t OFF_P1  = OFF_E1  + SZ_E1;
static const size_t OFF_E2  = OFF_P1  + SZ_P1;
static const size_t OFF_P2  = OFF_E2  + SZ_E2;
static const size_t OFF_SEQ = OFF_P2  + SZ_P2;
static const size_t OFF_LN  = OFF_SEQ + SZ_SEQ;
static const size_t OFF_QK  = OFF_LN  + SZ_LN;
static const size_t OFF_V   = OFF_QK  + SZ_QK;
static const size_t OFF_KINV= OFF_V   + SZ_V;
static const size_t OFF_AO  = OFF_KINV+ SZ_KINV;
static const size_t OFF_FFH = OFF_AO  + SZ_AO;
static const size_t OFF_BM  = OFF_FFH + SZ_FFH;
static const size_t OFF_UP1 = OFF_BM  + SZ_BM;
static const size_t OFF_D1  = OFF_UP1 + SZ_UP1;
static const size_t OFF_UP2 = OFF_D1  + SZ_D1;
static const size_t OFF_D2  = OFF_UP2 + SZ_UP2;
static const size_t ARENA_TOTAL = OFF_D2 + SZ_D2;

__device__ __align__(128) float g_arena[ARENA_TOTAL];

static const size_t IOFF_BUCKET = 0;
static const size_t IOFF_PERM   = 16384;
static const size_t IOFF_HIST   = 32768;
__device__ __align__(128) int g_ibuf[33280];

// ======================= implicit-GEMM conv3x3 (pad 1), FFMA2 ===============
__global__ void convg_kernel(const float* __restrict__ inA, int C1,
                             const float* __restrict__ inB, int C2,
                             const float* __restrict__ w, const float* __restrict__ bias,
                             float* __restrict__ out, int H, int W, int shiftW,
                             int OC, int act)
{
    __shared__ float As[16][68];    // [k][oc]
    __shared__ float Bs[16][132];   // [k][px]
    const int tid = threadIdx.x;
    const int m0 = blockIdx.y * 64;
    const int n0 = blockIdx.x * 128;
    const int C = C1 + C2;
    const int K = C * 9;
    const int HW = H * W;
    const int Wm1 = W - 1;
    const int la_m = tid >> 2;
    const int la_k = (tid & 3) * 4;
    const int lb_k = tid >> 5;
    const int lb_p = (tid & 31) * 4;
    const int tx = tid & 31;
    const int ty = tid >> 5;
    unsigned long long acc2[4][4];
    #pragma unroll
    for (int i = 0; i < 4; i++)
        #pragma unroll
        for (int j = 0; j < 4; j++) acc2[i][j] = 0ull;

    const int nk = (K + 15) >> 4;
    for (int kc = 0; kc < nk; kc++) {
        const int k0 = kc * 16;
        {
            int oc = m0 + la_m;
            #pragma unroll
            for (int u = 0; u < 4; u++) {
                int k = k0 + la_k + u;
                float v = 0.f;
                if (oc < OC && k < K) v = w[(size_t)oc * K + k];
                As[la_k + u][la_m] = v;
            }
        }
        #pragma unroll
        for (int r = 0; r < 2; r++) {
            int kk = lb_k + r * 8;
            int k = k0 + kk;
            float vals[4] = {0.f, 0.f, 0.f, 0.f};
            if (k < K) {
                int ci  = k / 9;
                int tap = k - ci * 9;
                int dy  = tap / 3 - 1;
                int dx  = tap - (tap / 3) * 3 - 1;
                const float* src = (ci < C1) ? (inA + (size_t)ci * HW)
                                             : (inB + (size_t)(ci - C1) * HW);
                #pragma unroll
                for (int u = 0; u < 4; u++) {
                    int p = n0 + lb_p + u;
                    int y = p >> shiftW, x = p & Wm1;
                    int yy = y + dy, xx = x + dx;
                    if (yy >= 0 && yy < H && xx >= 0 && xx < W)
                        vals[u] = src[(size_t)yy * W + xx];
                }
            }
            *(float4*)&Bs[kk][lb_p] = make_float4(vals[0], vals[1], vals[2], vals[3]);
        }
        __syncthreads();
        #pragma unroll
        for (int k = 0; k < 16; k++) {
            float4 a0 = *(const float4*)&As[k][ty * 8];
            float4 a1 = *(const float4*)&As[k][ty * 8 + 4];
            float4 b0 = *(const float4*)&Bs[k][tx * 4];
            unsigned long long ap[4] = { pack2(a0.x, a0.y), pack2(a0.z, a0.w),
                                         pack2(a1.x, a1.y), pack2(a1.z, a1.w) };
            unsigned long long bd[4] = { dup2(b0.x), dup2(b0.y), dup2(b0.z), dup2(b0.w) };
            #pragma unroll
            for (int i = 0; i < 4; i++)
                #pragma unroll
                for (int j = 0; j < 4; j++)
                    fma2(acc2[i][j], ap[i], bd[j]);
        }
        __syncthreads();
    }
    #pragma unroll
    for (int ip = 0; ip < 4; ip++) {
        float2 e0 = unpack2(acc2[ip][0]), e1 = unpack2(acc2[ip][1]);
        float2 e2 = unpack2(acc2[ip][2]), e3 = unpack2(acc2[ip][3]);
        float rows[2][4] = {{e0.x, e1.x, e2.x, e3.x}, {e0.y, e1.y, e2.y, e3.y}};
        #pragma unroll
        for (int s = 0; s < 2; s++) {
            int oc = m0 + ty * 8 + ip * 2 + s;
            if (oc < OC) {
                float b = bias[oc];
                float4 r;
                r.x = rows[s][0] + b; r.y = rows[s][1] + b;
                r.z = rows[s][2] + b; r.w = rows[s][3] + b;
                if (act == 0) {
                    r.x = fmaxf(r.x, 0.f); r.y = fmaxf(r.y, 0.f);
                    r.z = fmaxf(r.z, 0.f); r.w = fmaxf(r.w, 0.f);
                } else if (act == 2) {
                    r.x = 1.f / (1.f + expf(-r.x)); r.y = 1.f / (1.f + expf(-r.y));
                    r.z = 1.f / (1.f + expf(-r.z)); r.w = 1.f / (1.f + expf(-r.w));
                }
                *(float4*)(out + (size_t)oc * HW + n0 + tx * 4) = r;
            }
        }
    }
}

// ======================= implicit-GEMM ConvTranspose2d k=4 s=2 p=1, FFMA2 ====
__global__ void convtg_kernel(const float* __restrict__ in, const float* __restrict__ w,
                              const float* __restrict__ bias, float* __restrict__ out,
                              int Hin, int Win, int shiftWin, int IC, int OC)
{
    __shared__ float As[16][68];
    __shared__ float Bs[16][132];
    const int tid = threadIdx.x;
    const int m0 = blockIdx.y * 64;
    const int n0 = blockIdx.x * 128;
    const int py = blockIdx.z >> 1, px = blockIdx.z & 1;
    const int K = IC * 4;
    const int HWin = Hin * Win;
    const int Wout = Win * 2;
    const int Winm1 = Win - 1;
    const int la_m = tid >> 2;
    const int la_k = (tid & 3) * 4;
    const int lb_k = tid >> 5;
    const int lb_p = (tid & 31) * 4;
    const int tx = tid & 31;
    const int ty = tid >> 5;
    unsigned long long acc2[4][4];
    #pragma unroll
    for (int i = 0; i < 4; i++)
        #pragma unroll
        for (int j = 0; j < 4; j++) acc2[i][j] = 0ull;

    const int nk = K >> 4;
    for (int kc = 0; kc < nk; kc++) {
        const int k0 = kc * 16;
        {
            int oc = m0 + la_m;
            #pragma unroll
            for (int u = 0; u < 4; u++) {
                int k = k0 + la_k + u;
                int ic = k >> 2, ab = k & 3;
                int a = ab >> 1, b = ab & 1;
                int tap = (1 - py + 2 * a) * 4 + (1 - px + 2 * b);
                As[la_k + u][la_m] = w[((size_t)ic * OC + oc) * 16 + tap];
            }
        }
        #pragma unroll
        for (int r = 0; r < 2; r++) {
            int kk = lb_k + r * 8;
            int k = k0 + kk;
            int ic = k >> 2, ab = k & 3;
            int a = ab >> 1, b = ab & 1;
            int dy = py - a, dx = px - b;
            const float* src = in + (size_t)ic * HWin;
            float vals[4];
            #pragma unroll
            for (int u = 0; u < 4; u++) {
                int p = n0 + lb_p + u;
                int qy = p >> shiftWin, qx = p & Winm1;
                int iy = qy + dy, ix = qx + dx;
                vals[u] = (iy >= 0 && iy < Hin && ix >= 0 && ix < Win)
                          ? src[(size_t)iy * Win + ix] : 0.f;
            }
            *(float4*)&Bs[kk][lb_p] = make_float4(vals[0], vals[1], vals[2], vals[3]);
        }
        __syncthreads();
        #pragma unroll
        for (int k = 0; k < 16; k++) {
            float4 a0 = *(const float4*)&As[k][ty * 8];
            float4 a1 = *(const float4*)&As[k][ty * 8 + 4];
            float4 b0 = *(const float4*)&Bs[k][tx * 4];
            unsigned long long ap[4] = { pack2(a0.x, a0.y), pack2(a0.z, a0.w),
                                         pack2(a1.x, a1.y), pack2(a1.z, a1.w) };
            unsigned long long bd[4] = { dup2(b0.x), dup2(b0.y), dup2(b0.z), dup2(b0.w) };
            #pragma unroll
            for (int i = 0; i < 4; i++)
                #pragma unroll
                for (int j = 0; j < 4; j++)
                    fma2(acc2[i][j], ap[i], bd[j]);
        }
        __syncthreads();
    }
    const size_t HWout = (size_t)(Hin * 2) * Wout;
    #pragma unroll
    for (int ip = 0; ip < 4; ip++) {
        float2 e[4];
        #pragma unroll
        for (int j = 0; j < 4; j++) e[j] = unpack2(acc2[ip][j]);
        #pragma unroll
        for (int s = 0; s < 2; s++) {
            int oc = m0 + ty * 8 + ip * 2 + s;
            float b = bias[oc];
            float* op = out + (size_t)oc * HWout;
            #pragma unroll
            for (int j = 0; j < 4; j++) {
                int p = n0 + tx * 4 + j;
                int qy = p >> shiftWin, qx = p & Winm1;
                float v = (s == 0) ? e[j].x : e[j].y;
                op[(size_t)(2 * qy + py) * Wout + 2 * qx + px] = v + b;
            }
        }
    }
}

// ======================= conv 3x3 stencil (kept for OC=3 output conv) =======
__global__ void conv3x3_kernel(const float* __restrict__ inA, int C1,
                               const float* __restrict__ inB, int C2,
                               const float* __restrict__ w, const float* __restrict__ bias,
                               float* __restrict__ out, int H, int W, int OC, int act)
{
    __shared__ float tile[8][34][35];
    __shared__ float ws[8][8][9];
    const int tx = threadIdx.x, ty = threadIdx.y;
    const int t  = ty * 16 + tx;
    const int x0 = blockIdx.x * 32, y0 = blockIdx.y * 32;
    const int oc0 = blockIdx.z * 8;
    const int C = C1 + C2;
    float acc[4][8] = {};

    for (int c0 = 0; c0 < C; c0 += 8) {
        for (int i = t; i < 8 * 1156; i += 256) {
            int c = i / 1156, rem = i - c * 1156;
            int ry = rem / 34, rx = rem - ry * 34;
            int ci = c0 + c;
            float v = 0.f;
            if (ci < C) {
                const float* src = (ci < C1) ? (inA + (size_t)ci * H * W)
                                             : (inB + (size_t)(ci - C1) * H * W);
                int gy = y0 - 1 + ry, gx = x0 - 1 + rx;
                if (gy >= 0 && gy < H && gx >= 0 && gx < W) v = src[(size_t)gy * W + gx];
            }
            tile[c][ry][rx] = v;
        }
        for (int i = t; i < 576; i += 256) {
            int c = i / 72, rem = i - c * 72;
            int o = rem / 9, k = rem - o * 9;
            int ci = c0 + c, oc = oc0 + o;
            ws[c][o][k] = (ci < C && oc < OC) ? w[((size_t)oc * C + ci) * 9 + k] : 0.f;
        }
        __syncthreads();
        #pragma unroll
        for (int c = 0; c < 8; c++) {
            #pragma unroll
            for (int ky = 0; ky < 3; ky++)
                #pragma unroll
                for (int kx = 0; kx < 3; kx++) {
                    float v00 = tile[c][ty + ky]      [tx + kx];
                    float v01 = tile[c][ty + ky]      [tx + 16 + kx];
                    float v10 = tile[c][ty + 16 + ky] [tx + kx];
                    float v11 = tile[c][ty + 16 + ky] [tx + 16 + kx];
                    #pragma unroll
                    for (int o = 0; o < 8; o++) {
                        float wv = ws[c][o][ky * 3 + kx];
                        acc[0][o] = fmaf(v00, wv, acc[0][o]);
                        acc[1][o] = fmaf(v01, wv, acc[1][o]);
                        acc[2][o] = fmaf(v10, wv, acc[2][o]);
                        acc[3][o] = fmaf(v11, wv, acc[3][o]);
                    }
                }
        }
        __syncthreads();
    }
    #pragma unroll
    for (int p = 0; p < 4; p++) {
        int y = y0 + (p >> 1) * 16 + ty;
        int x = x0 + (p & 1) * 16 + tx;
        #pragma unroll
        for (int o = 0; o < 8; o++) {
            int oc = oc0 + o;
            if (oc < OC) {
                float r = acc[p][o] + bias[oc];
                if (act == 0) r = fmaxf(r, 0.f);
                else if (act == 2) r = 1.f / (1.f + expf(-r));
                out[(size_t)oc * H * W + (size_t)y * W + x] = r;
            }
        }
    }
}

// ======================= maxpool 2x2 stride 2 ================================
__global__ void maxpool_kernel(const float* __restrict__ in, float* __restrict__ out,
                               int C, int H, int W)
{
    int Ho = H >> 1, Wo = W >> 1;
    int idx = blockIdx.x * blockDim.x + threadIdx.x;
    int total = C * Ho * Wo;
    if (idx >= total) return;
    int x = idx % Wo, y = (idx / Wo) % Ho, c = idx / (Wo * Ho);
    const float* p = in + ((size_t)c * H + 2 * y) * W + 2 * x;
    out[idx] = fmaxf(fmaxf(p[0], p[1]), fmaxf(p[W], p[W + 1]));
}

// ======================= transpose (R x C) -> (C x R) ========================
__global__ void transpose_kernel(const float* __restrict__ in, float* __restrict__ out,
                                 int R, int C)
{
    __shared__ float tile[32][33];
    int bx = blockIdx.x * 32, by = blockIdx.y * 32;
    int x = bx + threadIdx.x;
    for (int i = threadIdx.y; i < 32; i += 8) {
        int y = by + i;
        tile[i][threadIdx.x] = in[(size_t)y * C + x];
    }
    __syncthreads();
    for (int i = threadIdx.y; i < 32; i += 8) {
        out[(size_t)(bx + i) * R + (by + threadIdx.x)] = tile[threadIdx.x][i];
    }
}

// ======================= LayerNorm over dim 256 ==============================
__global__ void ln_kernel(const float* __restrict__ in, float* __restrict__ out,
                          const float* __restrict__ g, const float* __restrict__ b)
{
    int row = blockIdx.x, tid = threadIdx.x;
    __shared__ float sm[8];
    float v = in[(size_t)row * 256 + tid];
    float s = v;
    #pragma unroll
    for (int o = 16; o; o >>= 1) s += __shfl_xor_sync(0xffffffffu, s, o);
    if ((tid & 31) == 0) sm[tid >> 5] = s;
    __syncthreads();
    float tot = 0.f;
    #pragma unroll
    for (int i = 0; i < 8; i++) tot += sm[i];
    float mean = tot * (1.f / 256.f);
    float c = v - mean;
    __syncthreads();
    float s2 = c * c;
    #pragma unroll
    for (int o = 16; o; o >>= 1) s2 += __shfl_xor_sync(0xffffffffu, s2, o);
    if ((tid & 31) == 0) sm[tid >> 5] = s2;
    __syncthreads();
    float tot2 = 0.f;
    #pragma unroll
    for (int i = 0; i < 8; i++) tot2 += sm[i];
    float var = tot2 * (1.f / 256.f);
    out[(size_t)row * 256 + tid] = c / sqrtf(var + 1e-5f) * g[tid] + b[tid];
}

// ======================= SGEMM 128x64 tile, 8x4 micro, FFMA2, dual-output ====
__global__ void sgemm_kernel(const float* __restrict__ A,
                             const float* __restrict__ B0, const float* __restrict__ bias0,
                             const float* __restrict__ res0, float* __restrict__ C0,
                             const float* __restrict__ B1, const float* __restrict__ bias1,
                             const float* __restrict__ res1, float* __restrict__ C1,
                             int M, int N, int K, int act)
{
    const float* __restrict__ B    = (blockIdx.z == 0) ? B0 : B1;
    const float* __restrict__ bias = (blockIdx.z == 0) ? bias0 : bias1;
    const float* __restrict__ res  = (blockIdx.z == 0) ? res0 : res1;
    float* __restrict__ C          = (blockIdx.z == 0) ? C0 : C1;
    __shared__ float As[2][16][132];
    __shared__ float Bs[2][16][64];
    const int tid = threadIdx.x;
    const int m0 = blockIdx.y * 128, n0 = blockIdx.x * 64;
    const int la_m = tid >> 1, la_k = (tid & 1) * 8;
    const int lb_k = tid >> 4, lb_n = (tid & 15) * 4;
    const int tx = tid & 15, ty = tid >> 4;
    const float* Ap = A + (size_t)(m0 + la_m) * K + la_k;
    const float* Bp = B + (size_t)lb_k * N + n0 + lb_n;
    unsigned long long acc2[4][4];
    #pragma unroll
    for (int i = 0; i < 4; i++)
        #pragma unroll
        for (int j = 0; j < 4; j++) acc2[i][j] = 0ull;
    float4 pa0 = *(const float4*)Ap;
    float4 pa1 = *(const float4*)(Ap + 4);
    float4 pb  = *(const float4*)Bp;
    As[0][la_k+0][la_m]=pa0.x; As[0][la_k+1][la_m]=pa0.y;
    As[0][la_k+2][la_m]=pa0.z; As[0][la_k+3][la_m]=pa0.w;
    As[0][la_k+4][la_m]=pa1.x; As[0][la_k+5][la_m]=pa1.y;
    As[0][la_k+6][la_m]=pa1.z; As[0][la_k+7][la_m]=pa1.w;
    *(float4*)&Bs[0][lb_k][lb_n] = pb;
    __syncthreads();
    const int nk = K >> 4;
    int buf = 0;
    for (int kc = 0; kc < nk; kc++) {
        if (kc + 1 < nk) {
            pa0 = *(const float4*)(Ap + (kc + 1) * 16);
            pa1 = *(const float4*)(Ap + (kc + 1) * 16 + 4);
            pb  = *(const float4*)(Bp + (size_t)(kc + 1) * 16 * N);
        }
        #pragma unroll
        for (int k = 0; k < 16; k++) {
            float4 a0 = *(const float4*)&As[buf][k][ty * 8];
            float4 a1 = *(const float4*)&As[buf][k][ty * 8 + 4];
            float4 b0 = *(const float4*)&Bs[buf][k][tx * 4];
            unsigned long long ap[4] = { pack2(a0.x, a0.y), pack2(a0.z, a0.w),
                                         pack2(a1.x, a1.y), pack2(a1.z, a1.w) };
            unsigned long long bd[4] = { dup2(b0.x), dup2(b0.y), dup2(b0.z), dup2(b0.w) };
            #pragma unroll
            for (int i = 0; i < 4; i++)
                #pragma unroll
                for (int j = 0; j < 4; j++)
                    fma2(acc2[i][j], ap[i], bd[j]);
        }
        if (kc + 1 < nk) {
            buf ^= 1;
            As[buf][la_k+0][la_m]=pa0.x; As[buf][la_k+1][la_m]=pa0.y;
            As[buf][la_k+2][la_m]=pa0.z; As[buf][la_k+3][la_m]=pa0.w;
            As[buf][la_k+4][la_m]=pa1.x; As[buf][la_k+5][la_m]=pa1.y;
            As[buf][la_k+6][la_m]=pa1.z; As[buf][la_k+7][la_m]=pa1.w;
            *(float4*)&Bs[buf][lb_k][lb_n] = pb;
            __syncthreads();
        }
    }
    float4 bi = *(const float4*)(bias + n0 + tx * 4);
    #pragma unroll
    for (int ip = 0; ip < 4; ip++) {
        float2 e0 = unpack2(acc2[ip][0]), e1 = unpack2(acc2[ip][1]);
        float2 e2 = unpack2(acc2[ip][2]), e3 = unpack2(acc2[ip][3]);
        float rows[2][4] = {{e0.x, e1.x, e2.x, e3.x}, {e0.y, e1.y, e2.y, e3.y}};
        #pragma unroll
        for (int s = 0; s < 2; s++) {
            int m = m0 + ty * 8 + ip * 2 + s;
            float4 r;
            r.x = rows[s][0] + bi.x; r.y = rows[s][1] + bi.y;
            r.z = rows[s][2] + bi.z; r.w = rows[s][3] + bi.w;
            if (act == 1) {
                float xs[4] = {r.x, r.y, r.z, r.w};
                #pragma unroll
                for (int j = 0; j < 4; j++) {
                    float x = xs[j];
                    xs[j] = 0.5f * x * (1.f + tanhf(0.7978845608f * (x + 0.044715f * x * x * x)));
                }
                r.x = xs[0]; r.y = xs[1]; r.z = xs[2]; r.w = xs[3];
            }
            if (res) {
                float4 rr = *(const float4*)(res + (size_t)m * N + n0 + tx * 4);
                r.x += rr.x; r.y += rr.y; r.z += rr.z; r.w += rr.w;
            }
            *(float4*)(C + (size_t)m * N + n0 + tx * 4) = r;
        }
    }
}

// ======================= SGEMM 128x128 tile, 8x8 micro, FFMA2 (for FF1) =====
__global__ void sgemm128_kernel(const float* __restrict__ A, const float* __restrict__ B,
                                const float* __restrict__ bias,
                                float* __restrict__ C, int M, int N, int K, int act)
{
    __shared__ float As[2][16][132];
    __shared__ float Bs[2][16][132];
    const int tid = threadIdx.x;
    const int m0 = blockIdx.y * 128, n0 = blockIdx.x * 128;
    const int la_m = tid >> 1, la_k = (tid & 1) * 8;
    const int lb_k = tid >> 4, lb_n = (tid & 15) * 8;
    const int tx = tid & 15, ty = tid >> 4;
    const float* Ap = A + (size_t)(m0 + la_m) * K + la_k;
    const float* Bp = B + (size_t)lb_k * N + n0 + lb_n;
    unsigned long long acc2[4][8];
    #pragma unroll
    for (int i = 0; i < 4; i++)
        #pragma unroll
        for (int j = 0; j < 8; j++) acc2[i][j] = 0ull;
    float4 pa0 = *(const float4*)Ap;
    float4 pa1 = *(const float4*)(Ap + 4);
    float4 pb0 = *(const float4*)Bp;
    float4 pb1 = *(const float4*)(Bp + 4);
    As[0][la_k+0][la_m]=pa0.x; As[0][la_k+1][la_m]=pa0.y;
    As[0][la_k+2][la_m]=pa0.z; As[0][la_k+3][la_m]=pa0.w;
    As[0][la_k+4][la_m]=pa1.x; As[0][la_k+5][la_m]=pa1.y;
    As[0][la_k+6][la_m]=pa1.z; As[0][la_k+7][la_m]=pa1.w;
    *(float4*)&Bs[0][lb_k][lb_n]     = pb0;
    *(float4*)&Bs[0][lb_k][lb_n + 4] = pb1;
    __syncthreads();
    const int nk = K >> 4;
    int buf = 0;
    for (int kc = 0; kc < nk; kc++) {
        if (kc + 1 < nk) {
            pa0 = *(const float4*)(Ap + (kc + 1) * 16);
            pa1 = *(const float4*)(Ap + (kc + 1) * 16 + 4);
            pb0 = *(const float4*)(Bp + (size_t)(kc + 1) * 16 * N);
            pb1 = *(const float4*)(Bp + (size_t)(kc + 1) * 16 * N + 4);
        }
        #pragma unroll
        for (int k = 0; k < 16; k++) {
            float4 a0 = *(const float4*)&As[buf][k][ty * 8];
            float4 a1 = *(const float4*)&As[buf][k][ty * 8 + 4];
            float4 b0 = *(const float4*)&Bs[buf][k][tx * 8];
            float4 b1 = *(const float4*)&Bs[buf][k][tx * 8 + 4];
            unsigned long long ap[4] = { pack2(a0.x, a0.y), pack2(a0.z, a0.w),
                                         pack2(a1.x, a1.y), pack2(a1.z, a1.w) };
            unsigned long long bd[8] = { dup2(b0.x), dup2(b0.y), dup2(b0.z), dup2(b0.w),
                                         dup2(b1.x), dup2(b1.y), dup2(b1.z), dup2(b1.w) };
            #pragma unroll
            for (int i = 0; i < 4; i++)
                #pragma unroll
                for (int j = 0; j < 8; j++)
                    fma2(acc2[i][j], ap[i], bd[j]);
        }
        if (kc + 1 < nk) {
            buf ^= 1;
            As[buf][la_k+0][la_m]=pa0.x; As[buf][la_k+1][la_m]=pa0.y;
            As[buf][la_k+2][la_m]=pa0.z; As[buf][la_k+3][la_m]=pa0.w;
            As[buf][la_k+4][la_m]=pa1.x; As[buf][la_k+5][la_m]=pa1.y;
            As[buf][la_k+6][la_m]=pa1.z; As[buf][la_k+7][la_m]=pa1.w;
            *(float4*)&Bs[buf][lb_k][lb_n]     = pb0;
            *(float4*)&Bs[buf][lb_k][lb_n + 4] = pb1;
            __syncthreads();
        }
    }
    float4 bi0 = *(const float4*)(bias + n0 + tx * 8);
    float4 bi1 = *(const float4*)(bias + n0 + tx * 8 + 4);
    float bb[8] = {bi0.x, bi0.y, bi0.z, bi0.w, bi1.x, bi1.y, bi1.z, bi1.w};
    #pragma unroll
    for (int ip = 0; ip < 4; ip++) {
        float2 e[8];
        #pragma unroll
        for (int j = 0; j < 8; j++) e[j] = unpack2(acc2[ip][j]);
        #pragma unroll
        for (int s = 0; s < 2; s++) {
            int m = m0 + ty * 8 + ip * 2 + s;
            float xs[8];
            #pragma unroll
            for (int j = 0; j < 8; j++) {
                float x = ((s == 0) ? e[j].x : e[j].y) + bb[j];
                if (act == 1)
                    x = 0.5f * x * (1.f + tanhf(0.7978845608f * (x + 0.044715f * x * x * x)));
                xs[j] = x;
            }
            *(float4*)(C + (size_t)m * N + n0 + tx * 8)     = make_float4(xs[0], xs[1], xs[2], xs[3]);
            *(float4*)(C + (size_t)m * N + n0 + tx * 8 + 4) = make_float4(xs[4], xs[5], xs[6], xs[7]);
        }
    }
}

// ======================= LSH bucketing + histogram ===========================
__global__ void bucket_kernel(const float* __restrict__ qk, const float* __restrict__ rot,
                              float* __restrict__ kinv, int* __restrict__ bucket,
                              int* __restrict__ hist)
{
    int n = blockIdx.x, h = blockIdx.y, lane = threadIdx.x;
    __shared__ float q[64];
    float q0 = qk[(size_t)n * 256 + h * 64 + lane];
    float q1 = qk[(size_t)n * 256 + h * 64 + 32 + lane];
    q[lane] = q0; q[lane + 32] = q1;
    __syncwarp();
    float ss = q0 * q0 + q1 * q1;
    #pragma unroll
    for (int o = 16; o; o >>= 1) ss += __shfl_xor_sync(0xffffffffu, ss, o);
    if (lane == 0) kinv[h * 4096 + n] = 1.f / (sqrtf(ss) + 1e-6f);

    float acc = 0.f;
    const float* rp = rot + (size_t)h * 64 * 32 + lane;
    #pragma unroll 8
    for (int d = 0; d < 64; d++) acc = fmaf(q[d], rp[(size_t)d * 32], acc);
    float bv = acc; int bi = lane;
    if (-acc > bv) { bv = -acc; bi = lane + 32; }
    #pragma unroll
    for (int o = 16; o; o >>= 1) {
        float ov = __shfl_xor_sync(0xffffffffu, bv, o);
        int oi = __shfl_xor_sync(0xffffffffu, bi, o);
        if (ov > bv || (ov == bv && oi < bi)) { bv = ov; bi = oi; }
    }
    if (lane == 0) {
        bucket[h * 4096 + n] = bi;
        atomicAdd(&hist[(h << 6) + bi], 1);
    }
}

// stable counting-sort scatter (prefix computed in-block from hist)
__global__ void scatter_kernel(const int* __restrict__ bucket, const int* __restrict__ hist,
                               int* __restrict__ perm)
{
    int b = blockIdx.x, h = blockIdx.y, lane = threadIdx.x;
    int base = 0;
    for (int i = lane; i < b; i += 32) base += hist[h * 64 + i];
    #pragma unroll
    for (int o = 16; o; o >>= 1) base += __shfl_xor_sync(0xffffffffu, base, o);
    const int* bk = bucket + h * 4096;
    for (int n0 = 0; n0 < 4096; n0 += 32) {
        int v = bk[n0 + lane];
        unsigned m = __ballot_sync(0xffffffffu, v == b);
        if (v == b)
            perm[h * 4096 + base + __popc(m & ((1u << lane) - 1u))] = n0 + lane;
        base += __popc(m);
    }
}

// ======================= fused attention: dots + softmax + attn@V ============
// Phase A: probs P[64][128] in smem (identical arithmetic to old dots_kernel).
// Phase B: attn@V consuming P from smem (identical j-order to old av_kernel).
__global__ void attn_kernel(const float* __restrict__ qk, const float* __restrict__ kinv,
                            const float* __restrict__ v, const int* __restrict__ perm,
                            float* __restrict__ out)
{
    __shared__ float P[64][132];
    __shared__ float qs[16][68];
    __shared__ float ks[16][132];   // reused as V-stage Bs[16][68] in phase B
    __shared__ int tok[128];
    __shared__ float kiv[128];
    int c = blockIdx.x, h = blockIdx.y, tid = threadIdx.x;
    int cprev = (c + 63) & 63;
    if (tid < 128) {
        int p = (tid < 64) ? c * 64 + tid : cprev * 64 + (tid - 64);
        int t = perm[h * 4096 + p];
        tok[tid] = t;
        kiv[tid] = kinv[h * 4096 + t];
    }
    __syncthreads();
    // ---- phase A: dots + softmax ----
    {
        const int tx = tid & 15, ty = tid >> 4;
        float acc[4][8] = {};
        for (int d0 = 0; d0 < 64; d0 += 16) {
            {
                int q = tid & 63, dsub = tid >> 6;
                float4 v4 = *(const float4*)(qk + (size_t)tok[q] * 256 + h * 64 + d0 + dsub * 4);
                qs[dsub*4+0][q] = v4.x; qs[dsub*4+1][q] = v4.y;
                qs[dsub*4+2][q] = v4.z; qs[dsub*4+3][q] = v4.w;
            }
            #pragma unroll
            for (int r = 0; r < 2; r++) {
                int idx = tid + r * 256;
                int j = idx & 127, dsub = idx >> 7;
                float sc = kiv[j];
                float4 v4 = *(const float4*)(qk + (size_t)tok[j] * 256 + h * 64 + d0 + dsub * 4);
                ks[dsub*4+0][j] = v4.x * sc; ks[dsub*4+1][j] = v4.y * sc;
                ks[dsub*4+2][j] = v4.z * sc; ks[dsub*4+3][j] = v4.w * sc;
            }
            __syncthreads();
            #pragma unroll
            for (int d = 0; d < 16; d++) {
                float4 q0 = *(const float4*)&qs[d][ty * 4];
                float4 k0 = *(const float4*)&ks[d][tx * 8];
                float4 k1 = *(const float4*)&ks[d][tx * 8 + 4];
                float qq[4] = {q0.x, q0.y, q0.z, q0.w};
                float kk[8] = {k0.x, k0.y, k0.z, k0.w, k1.x, k1.y, k1.z, k1.w};
                #pragma unroll
                for (int i = 0; i < 4; i++)
                    #pragma unroll
                    for (int j = 0; j < 8; j++)
                        acc[i][j] = fmaf(qq[i], kk[j], acc[i][j]);
            }
            __syncthreads();
        }
        #pragma unroll
        for (int i = 0; i < 4; i++) {
            int ii = ty * 4 + i;
            int ti = tok[ii];
            float vv[8];
            float mx = -3.402823e38f;
            #pragma unroll
            for (int j = 0; j < 8; j++) {
                float x = acc[i][j] * 0.125f;
                if (ti == tok[tx * 8 + j]) x = -1e5f;
                vv[j] = x;
                mx = fmaxf(mx, x);
            }
            #pragma unroll
            for (int o = 1; o < 16; o <<= 1) mx = fmaxf(mx, __shfl_xor_sync(0xffffffffu, mx, o));
            float s = 0.f;
            #pragma unroll
            for (int j = 0; j < 8; j++) { vv[j] = expf(vv[j] - mx); s += vv[j]; }
            #pragma unroll
            for (int o = 1; o < 16; o <<= 1) s += __shfl_xor_sync(0xffffffffu, s, o);
            float inv = 1.f / s;
            *(float4*)&P[ii][tx * 8]     = make_float4(vv[0]*inv, vv[1]*inv, vv[2]*inv, vv[3]*inv);
            *(float4*)&P[ii][tx * 8 + 4] = make_float4(vv[4]*inv, vv[5]*inv, vv[6]*inv, vv[7]*inv);
        }
    }
    __syncthreads();
    // ---- phase B: attn @ V ----
    {
        const int tx = tid & 7, ty = tid >> 3;
        float* Bs = &ks[0][0];   // [16][68] layout
        float acc[2][8] = {};
        for (int j0 = 0; j0 < 128; j0 += 16) {
            {
                int k = tid >> 4, dsub = tid & 15;
                float4 v4 = *(const float4*)(v + (size_t)tok[j0 + k] * 256 + h * 64 + dsub * 4);
                *(float4*)&Bs[k * 68 + dsub * 4] = v4;
            }
            __syncthreads();
            #pragma unroll
            for (int k = 0; k < 16; k++) {
                float a0 = P[ty * 2][j0 + k], a1 = P[ty * 2 + 1][j0 + k];
                float4 b0 = *(const float4*)&Bs[k * 68 + tx * 8];
                float4 b1 = *(const float4*)&Bs[k * 68 + tx * 8 + 4];
                float bb[8] = {b0.x, b0.y, b0.z, b0.w, b1.x, b1.y, b1.z, b1.w};
                #pragma unroll
                for (int j = 0; j < 8; j++) {
                    acc[0][j] = fmaf(a0, bb[j], acc[0][j]);
                    acc[1][j] = fmaf(a1, bb[j], acc[1][j]);
                }
            }
            __syncthreads();
        }
        #pragma unroll
        for (int r = 0; r < 2; r++) {
            int ii = ty * 2 + r;
            float* op = out + (size_t)tok[ii] * 256 + h * 64 + tx * 8;
            *(float4*)op       = make_float4(acc[r][0], acc[r][1], acc[r][2], acc[r][3]);
            *(float4*)(op + 4) = make_float4(acc[r][4], acc[r][5], acc[r][6], acc[r][7]);
        }
    }
}

// ======================= host launch ========================================
extern "C" void kernel_launch(void* const* d_in, const int* in_sizes, int n_in,
                              void* d_out, int out_size)
{
    (void)in_sizes; (void)n_in; (void)out_size;
    const float* burst   = (const float*)d_in[0];
    const float* conv1_w = (const float*)d_in[1];
    const float* conv1_b = (const float*)d_in[2];
    const float* conv2_w = (const float*)d_in[3];
    const float* conv2_b = (const float*)d_in[4];
    const float* conv3_w = (const float*)d_in[5];
    const float* conv3_b = (const float*)d_in[6];
    const float* ln1_g   = (const float*)d_in[7];
    const float* ln1_b   = (const float*)d_in[8];
    const float* Wqk     = (const float*)d_in[9];
    const float* bqk     = (const float*)d_in[10];
    const float* Wv      = (const float*)d_in[11];
    const float* bv      = (const float*)d_in[12];
    const float* Wo      = (const float*)d_in[13];
    const float* bo      = (const float*)d_in[14];
    const float* rot     = (const float*)d_in[15];
    const float* ln2_g   = (const float*)d_in[16];
    const float* ln2_b   = (const float*)d_in[17];
    const float* Wff1    = (const float*)d_in[18];
    const float* bff1    = (const float*)d_in[19];
    const float* Wff2    = (const float*)d_in[20];
    const float* bff2    = (const float*)d_in[21];
    const float* up1_w   = (const float*)d_in[22];
    const float* up1_b   = (const float*)d_in[23];
    const float* dec1_w  = (const float*)d_in[24];
    const float* dec1_b  = (const float*)d_in[25];
    const float* up2_w   = (const float*)d_in[26];
    const float* up2_b   = (const float*)d_in[27];
    const float* dec2_w  = (const float*)d_in[28];
    const float* dec2_b  = (const float*)d_in[29];
    const float* out_w   = (const float*)d_in[30];
    const float* out_b   = (const float*)d_in[31];

    float* AR = nullptr; int* IB = nullptr;
    cudaGetSymbolAddress((void**)&AR, g_arena);
    cudaGetSymbolAddress((void**)&IB, g_ibuf);

    float* E1  = AR + OFF_E1;   float* P1  = AR + OFF_P1;
    float* E2  = AR + OFF_E2;   float* P2  = AR + OFF_P2;
    float* SEQ = AR + OFF_SEQ;  float* LNB = AR + OFF_LN;
    float* QK  = AR + OFF_QK;   float* V   = AR + OFF_V;
    float* KINV= AR + OFF_KINV;
    float* AO  = AR + OFF_AO;   float* FFH = AR + OFF_FFH;
    float* BM  = AR + OFF_BM;   float* UP1 = AR + OFF_UP1;
    float* D1  = AR + OFF_D1;   float* UP2 = AR + OFF_UP2;
    float* D2  = AR + OFF_D2;
    int* BKT = IB + IOFF_BUCKET; int* PRM = IB + IOFF_PERM;
    int* HST = IB + IOFF_HIST;

    dim3 b16(16, 16);

    // -------- encoder (implicit-GEMM convs) --------
    convg_kernel<<<dim3(512, 1), 256>>>(burst, 3, nullptr, 0, conv1_w, conv1_b, E1, 256, 256, 8, 64, 0);
    maxpool_kernel<<<(64 * 128 * 128 + 255) / 256, 256>>>(E1, P1, 64, 256, 256);
    convg_kernel<<<dim3(128, 2), 256>>>(P1, 64, nullptr, 0, conv2_w, conv2_b, E2, 128, 128, 7, 128, 0);
    maxpool_kernel<<<(128 * 64 * 64 + 255) / 256, 256>>>(E2, P2, 128, 128, 128);
    convg_kernel<<<dim3(32, 4), 256>>>(P2, 128, nullptr, 0, conv3_w, conv3_b, BM, 64, 64, 6, 256, 0);
    transpose_kernel<<<dim3(128, 8), dim3(32, 8)>>>(BM, SEQ, 256, 4096);

    // -------- reformer (4 layers) --------
    for (int l = 0; l < 4; l++) {
        ln_kernel<<<4096, 256>>>(SEQ, LNB, ln1_g + l * 256, ln1_b + l * 256);
        sgemm_kernel<<<dim3(4, 32, 2), 256>>>(LNB,
            Wqk + (size_t)l * 65536, bqk + l * 256, nullptr, QK,
            Wv  + (size_t)l * 65536, bv  + l * 256, nullptr, V,
            4096, 256, 256, 0);
        cudaMemsetAsync(HST, 0, 256 * sizeof(int));
        bucket_kernel<<<dim3(4096, 4), 32>>>(QK, rot + (size_t)l * 4 * 64 * 32, KINV, BKT, HST);
        scatter_kernel<<<dim3(64, 4), 32>>>(BKT, HST, PRM);
        attn_kernel<<<dim3(64, 4), 256>>>(QK, KINV, V, PRM, AO);
        sgemm_kernel<<<dim3(4, 32, 1), 256>>>(AO,
            Wo + (size_t)l * 65536, bo + l * 256, SEQ, SEQ,
            nullptr, nullptr, nullptr, nullptr,
            4096, 256, 256, 0);
        ln_kernel<<<4096, 256>>>(SEQ, LNB, ln2_g + l * 256, ln2_b + l * 256);
        sgemm128_kernel<<<dim3(8, 32), 256>>>(LNB, Wff1 + (size_t)l * 262144, bff1 + l * 1024, FFH, 4096, 1024, 256, 1);
        sgemm_kernel<<<dim3(4, 32, 1), 256>>>(FFH,
            Wff2 + (size_t)l * 262144, bff2 + l * 256, SEQ, SEQ,
            nullptr, nullptr, nullptr, nullptr,
            4096, 256, 1024, 0);
    }

    // -------- decoder (implicit-GEMM convT + convs) --------
    transpose_kernel<<<dim3(8, 128), dim3(32, 8)>>>(SEQ, BM, 4096, 256);
    convtg_kernel<<<dim3(32, 2, 4), 256>>>(BM, up1_w, up1_b, UP1, 64, 64, 6, 256, 128);
    convg_kernel<<<dim3(128, 2), 256>>>(UP1, 128, E2, 128, dec1_w, dec1_b, D1, 128, 128, 7, 128, 0);
    convtg_kernel<<<dim3(128, 1, 4), 256>>>(D1, up2_w, up2_b, UP2, 128, 128, 7, 128, 64);
    convg_kernel<<<dim3(512, 1), 256>>>(UP2, 64, E1, 64, dec2_w, dec2_b, D2, 256, 256, 8, 64, 0);
    conv3x3_kernel<<<dim3(8, 8, 1), b16>>>(D2, 64, nullptr, 0, out_w, out_b, (float*)d_out, 256, 256, 3, 2);
}

// round 17
// speedup vs baseline: 1.5534x; 1.5534x over previous
#include <cuda_runtime.h>
#include <math.h>
#include <stddef.h>

// ======================= packed fp32x2 helpers (Blackwell FFMA2) =============
__device__ __forceinline__ unsigned long long pack2(float lo, float hi) {
    unsigned long long r;
    asm("mov.b64 %0, {%1, %2};" : "=l"(r) : "f"(lo), "f"(hi));
    return r;
}
__device__ __forceinline__ unsigned long long dup2(float v) {
    unsigned long long r;
    asm("mov.b64 %0, {%1, %1};" : "=l"(r) : "f"(v));
    return r;
}
__device__ __forceinline__ void fma2(unsigned long long& acc, unsigned long long a,
                                     unsigned long long b) {
    asm("fma.rn.f32x2 %0, %1, %2, %3;" : "=l"(acc) : "l"(a), "l"(b), "l"(acc));
}
__device__ __forceinline__ float2 unpack2(unsigned long long v) {
    float lo, hi;
    asm("mov.b64 {%0, %1}, %2;" : "=f"(lo), "=f"(hi) : "l"(v));
    return make_float2(lo, hi);
}

// ======================= scratch arena (no allocations) =======================
static const size_t SZ_E1  = 64ull*256*256;
static const size_t SZ_P1  = 64ull*128*128;
static const size_t SZ_E2  = 128ull*128*128;
static const size_t SZ_P2  = 128ull*64*64;
static const size_t SZ_SEQ = 4096ull*256;
static const size_t SZ_LN  = 4096ull*256;
static const size_t SZ_QK  = 4096ull*256;
static const size_t SZ_V   = 4096ull*256;
static const size_t SZ_KINV= 4ull*4096;
static const size_t SZ_DOTS= 4ull*64*64*128;
static const size_t SZ_AO  = 4096ull*256;
static const size_t SZ_FFH = 4096ull*1024;
static const size_t SZ_BM  = 256ull*4096;
static const size_t SZ_UP1 = 128ull*128*128;
static const size_t SZ_D1  = 128ull*128*128;
static const size_t SZ_UP2 = 64ull*256*256;
static const size_t SZ_D2  = 64ull*256*256;

static const size_t OFF_E1  = 0;
static const size_t OFF_P1  = OFF_E1  + SZ_E1;
static const size_t OFF_E2  = OFF_P1  + SZ_P1;
static const size_t OFF_P2  = OFF_E2  + SZ_E2;
static const size_t OFF_SEQ = OFF_P2  + SZ_P2;
static const size_t OFF_LN  = OFF_SEQ + SZ_SEQ;
static const size_t OFF_QK  = OFF_LN  + SZ_LN;
static const size_t OFF_V   = OFF_QK  + SZ_QK;
static const size_t OFF_KINV= OFF_V   + SZ_V;
static const size_t OFF_DOTS= OFF_KINV+ SZ_KINV;
static const size_t OFF_AO  = OFF_DOTS+ SZ_DOTS;
static const size_t OFF_FFH = OFF_AO  + SZ_AO;
static const size_t OFF_BM  = OFF_FFH + SZ_FFH;
static const size_t OFF_UP1 = OFF_BM  + SZ_BM;
static const size_t OFF_D1  = OFF_UP1 + SZ_UP1;
static const size_t OFF_UP2 = OFF_D1  + SZ_D1;
static const size_t OFF_D2  = OFF_UP2 + SZ_UP2;
static const size_t ARENA_TOTAL = OFF_D2 + SZ_D2;

__device__ __align__(128) float g_arena[ARENA_TOTAL];

static const size_t IOFF_BUCKET = 0;
static const size_t IOFF_PERM   = 16384;
static const size_t IOFF_HIST   = 32768;
__device__ __align__(128) int g_ibuf[33280];

// ======================= implicit-GEMM conv3x3 (pad 1), FFMA2 ===============
__global__ void convg_kernel(const float* __restrict__ inA, int C1,
                             const float* __restrict__ inB, int C2,
                             const float* __restrict__ w, const float* __restrict__ bias,
                             float* __restrict__ out, int H, int W, int shiftW,
                             int OC, int act)
{
    __shared__ float As[16][68];    // [k][oc]
    __shared__ float Bs[16][132];   // [k][px]
    const int tid = threadIdx.x;
    const int m0 = blockIdx.y * 64;
    const int n0 = blockIdx.x * 128;
    const int C = C1 + C2;
    const int K = C * 9;
    const int HW = H * W;
    const int Wm1 = W - 1;
    const int la_m = tid >> 2;
    const int la_k = (tid & 3) * 4;
    const int lb_k = tid >> 5;
    const int lb_p = (tid & 31) * 4;
    const int tx = tid & 31;
    const int ty = tid >> 5;
    unsigned long long acc2[4][4];
    #pragma unroll
    for (int i = 0; i < 4; i++)
        #pragma unroll
        for (int j = 0; j < 4; j++) acc2[i][j] = 0ull;

    const int nk = (K + 15) >> 4;
    for (int kc = 0; kc < nk; kc++) {
        const int k0 = kc * 16;
        {
            int oc = m0 + la_m;
            #pragma unroll
            for (int u = 0; u < 4; u++) {
                int k = k0 + la_k + u;
                float v = 0.f;
                if (oc < OC && k < K) v = w[(size_t)oc * K + k];
                As[la_k + u][la_m] = v;
            }
        }
        #pragma unroll
        for (int r = 0; r < 2; r++) {
            int kk = lb_k + r * 8;
            int k = k0 + kk;
            float vals[4] = {0.f, 0.f, 0.f, 0.f};
            if (k < K) {
                int ci  = k / 9;
                int tap = k - ci * 9;
                int dy  = tap / 3 - 1;
                int dx  = tap - (tap / 3) * 3 - 1;
                const float* src = (ci < C1) ? (inA + (size_t)ci * HW)
                                             : (inB + (size_t)(ci - C1) * HW);
                #pragma unroll
                for (int u = 0; u < 4; u++) {
                    int p = n0 + lb_p + u;
                    int y = p >> shiftW, x = p & Wm1;
                    int yy = y + dy, xx = x + dx;
                    if (yy >= 0 && yy < H && xx >= 0 && xx < W)
                        vals[u] = src[(size_t)yy * W + xx];
                }
            }
            *(float4*)&Bs[kk][lb_p] = make_float4(vals[0], vals[1], vals[2], vals[3]);
        }
        __syncthreads();
        #pragma unroll
        for (int k = 0; k < 16; k++) {
            float4 a0 = *(const float4*)&As[k][ty * 8];
            float4 a1 = *(const float4*)&As[k][ty * 8 + 4];
            float4 b0 = *(const float4*)&Bs[k][tx * 4];
            unsigned long long ap[4] = { pack2(a0.x, a0.y), pack2(a0.z, a0.w),
                                         pack2(a1.x, a1.y), pack2(a1.z, a1.w) };
            unsigned long long bd[4] = { dup2(b0.x), dup2(b0.y), dup2(b0.z), dup2(b0.w) };
            #pragma unroll
            for (int i = 0; i < 4; i++)
                #pragma unroll
                for (int j = 0; j < 4; j++)
                    fma2(acc2[i][j], ap[i], bd[j]);
        }
        __syncthreads();
    }
    #pragma unroll
    for (int ip = 0; ip < 4; ip++) {
        float2 e0 = unpack2(acc2[ip][0]), e1 = unpack2(acc2[ip][1]);
        float2 e2 = unpack2(acc2[ip][2]), e3 = unpack2(acc2[ip][3]);
        float rows[2][4] = {{e0.x, e1.x, e2.x, e3.x}, {e0.y, e1.y, e2.y, e3.y}};
        #pragma unroll
        for (int s = 0; s < 2; s++) {
            int oc = m0 + ty * 8 + ip * 2 + s;
            if (oc < OC) {
                float b = bias[oc];
                float4 r;
                r.x = rows[s][0] + b; r.y = rows[s][1] + b;
                r.z = rows[s][2] + b; r.w = rows[s][3] + b;
                if (act == 0) {
                    r.x = fmaxf(r.x, 0.f); r.y = fmaxf(r.y, 0.f);
                    r.z = fmaxf(r.z, 0.f); r.w = fmaxf(r.w, 0.f);
                } else if (act == 2) {
                    r.x = 1.f / (1.f + expf(-r.x)); r.y = 1.f / (1.f + expf(-r.y));
                    r.z = 1.f / (1.f + expf(-r.z)); r.w = 1.f / (1.f + expf(-r.w));
                }
                *(float4*)(out + (size_t)oc * HW + n0 + tx * 4) = r;
            }
        }
    }
}

// ======================= implicit-GEMM ConvTranspose2d k=4 s=2 p=1, FFMA2 ====
__global__ void convtg_kernel(const float* __restrict__ in, const float* __restrict__ w,
                              const float* __restrict__ bias, float* __restrict__ out,
                              int Hin, int Win, int shiftWin, int IC, int OC)
{
    __shared__ float As[16][68];
    __shared__ float Bs[16][132];
    const int tid = threadIdx.x;
    const int m0 = blockIdx.y * 64;
    const int n0 = blockIdx.x * 128;
    const int py = blockIdx.z >> 1, px = blockIdx.z & 1;
    const int K = IC * 4;
    const int HWin = Hin * Win;
    const int Wout = Win * 2;
    const int Winm1 = Win - 1;
    const int la_m = tid >> 2;
    const int la_k = (tid & 3) * 4;
    const int lb_k = tid >> 5;
    const int lb_p = (tid & 31) * 4;
    const int tx = tid & 31;
    const int ty = tid >> 5;
    unsigned long long acc2[4][4];
    #pragma unroll
    for (int i = 0; i < 4; i++)
        #pragma unroll
        for (int j = 0; j < 4; j++) acc2[i][j] = 0ull;

    const int nk = K >> 4;
    for (int kc = 0; kc < nk; kc++) {
        const int k0 = kc * 16;
        {
            int oc = m0 + la_m;
            #pragma unroll
            for (int u = 0; u < 4; u++) {
                int k = k0 + la_k + u;
                int ic = k >> 2, ab = k & 3;
                int a = ab >> 1, b = ab & 1;
                int tap = (1 - py + 2 * a) * 4 + (1 - px + 2 * b);
                As[la_k + u][la_m] = w[((size_t)ic * OC + oc) * 16 + tap];
            }
        }
        #pragma unroll
        for (int r = 0; r < 2; r++) {
            int kk = lb_k + r * 8;
            int k = k0 + kk;
            int ic = k >> 2, ab = k & 3;
            int a = ab >> 1, b = ab & 1;
            int dy = py - a, dx = px - b;
            const float* src = in + (size_t)ic * HWin;
            float vals[4];
            #pragma unroll
            for (int u = 0; u < 4; u++) {
                int p = n0 + lb_p + u;
                int qy = p >> shiftWin, qx = p & Winm1;
                int iy = qy + dy, ix = qx + dx;
                vals[u] = (iy >= 0 && iy < Hin && ix >= 0 && ix < Win)
                          ? src[(size_t)iy * Win + ix] : 0.f;
            }
            *(float4*)&Bs[kk][lb_p] = make_float4(vals[0], vals[1], vals[2], vals[3]);
        }
        __syncthreads();
        #pragma unroll
        for (int k = 0; k < 16; k++) {
            float4 a0 = *(const float4*)&As[k][ty * 8];
            float4 a1 = *(const float4*)&As[k][ty * 8 + 4];
            float4 b0 = *(const float4*)&Bs[k][tx * 4];
            unsigned long long ap[4] = { pack2(a0.x, a0.y), pack2(a0.z, a0.w),
                                         pack2(a1.x, a1.y), pack2(a1.z, a1.w) };
            unsigned long long bd[4] = { dup2(b0.x), dup2(b0.y), dup2(b0.z), dup2(b0.w) };
            #pragma unroll
            for (int i = 0; i < 4; i++)
                #pragma unroll
                for (int j = 0; j < 4; j++)
                    fma2(acc2[i][j], ap[i], bd[j]);
        }
        __syncthreads();
    }
    const size_t HWout = (size_t)(Hin * 2) * Wout;
    #pragma unroll
    for (int ip = 0; ip < 4; ip++) {
        float2 e[4];
        #pragma unroll
        for (int j = 0; j < 4; j++) e[j] = unpack2(acc2[ip][j]);
        #pragma unroll
        for (int s = 0; s < 2; s++) {
            int oc = m0 + ty * 8 + ip * 2 + s;
            float b = bias[oc];
            float* op = out + (size_t)oc * HWout;
            #pragma unroll
            for (int j = 0; j < 4; j++) {
                int p = n0 + tx * 4 + j;
                int qy = p >> shiftWin, qx = p & Winm1;
                float v = (s == 0) ? e[j].x : e[j].y;
                op[(size_t)(2 * qy + py) * Wout + 2 * qx + px] = v + b;
            }
        }
    }
}

// ======================= conv 3x3 stencil (kept for OC=3 output conv) =======
__global__ void conv3x3_kernel(const float* __restrict__ inA, int C1,
                               const float* __restrict__ inB, int C2,
                               const float* __restrict__ w, const float* __restrict__ bias,
                               float* __restrict__ out, int H, int W, int OC, int act)
{
    __shared__ float tile[8][34][35];
    __shared__ float ws[8][8][9];
    const int tx = threadIdx.x, ty = threadIdx.y;
    const int t  = ty * 16 + tx;
    const int x0 = blockIdx.x * 32, y0 = blockIdx.y * 32;
    const int oc0 = blockIdx.z * 8;
    const int C = C1 + C2;
    float acc[4][8] = {};

    for (int c0 = 0; c0 < C; c0 += 8) {
        for (int i = t; i < 8 * 1156; i += 256) {
            int c = i / 1156, rem = i - c * 1156;
            int ry = rem / 34, rx = rem - ry * 34;
            int ci = c0 + c;
            float v = 0.f;
            if (ci < C) {
                const float* src = (ci < C1) ? (inA + (size_t)ci * H * W)
                                             : (inB + (size_t)(ci - C1) * H * W);
                int gy = y0 - 1 + ry, gx = x0 - 1 + rx;
                if (gy >= 0 && gy < H && gx >= 0 && gx < W) v = src[(size_t)gy * W + gx];
            }
            tile[c][ry][rx] = v;
        }
        for (int i = t; i < 576; i += 256) {
            int c = i / 72, rem = i - c * 72;
            int o = rem / 9, k = rem - o * 9;
            int ci = c0 + c, oc = oc0 + o;
            ws[c][o][k] = (ci < C && oc < OC) ? w[((size_t)oc * C + ci) * 9 + k] : 0.f;
        }
        __syncthreads();
        #pragma unroll
        for (int c = 0; c < 8; c++) {
            #pragma unroll
            for (int ky = 0; ky < 3; ky++)
                #pragma unroll
                for (int kx = 0; kx < 3; kx++) {
                    float v00 = tile[c][ty + ky]      [tx + kx];
                    float v01 = tile[c][ty + ky]      [tx + 16 + kx];
                    float v10 = tile[c][ty + 16 + ky] [tx + kx];
                    float v11 = tile[c][ty + 16 + ky] [tx + 16 + kx];
                    #pragma unroll
                    for (int o = 0; o < 8; o++) {
                        float wv = ws[c][o][ky * 3 + kx];
                        acc[0][o] = fmaf(v00, wv, acc[0][o]);
                        acc[1][o] = fmaf(v01, wv, acc[1][o]);
                        acc[2][o] = fmaf(v10, wv, acc[2][o]);
                        acc[3][o] = fmaf(v11, wv, acc[3][o]);
                    }
                }
        }
        __syncthreads();
    }
    #pragma unroll
    for (int p = 0; p < 4; p++) {
        int y = y0 + (p >> 1) * 16 + ty;
        int x = x0 + (p & 1) * 16 + tx;
        #pragma unroll
        for (int o = 0; o < 8; o++) {
            int oc = oc0 + o;
            if (oc < OC) {
                float r = acc[p][o] + bias[oc];
                if (act == 0) r = fmaxf(r, 0.f);
                else if (act == 2) r = 1.f / (1.f + expf(-r));
                out[(size_t)oc * H * W + (size_t)y * W + x] = r;
            }
        }
    }
}

// ======================= maxpool 2x2 stride 2 ================================
__global__ void maxpool_kernel(const float* __restrict__ in, float* __restrict__ out,
                               int C, int H, int W)
{
    int Ho = H >> 1, Wo = W >> 1;
    int idx = blockIdx.x * blockDim.x + threadIdx.x;
    int total = C * Ho * Wo;
    if (idx >= total) return;
    int x = idx % Wo, y = (idx / Wo) % Ho, c = idx / (Wo * Ho);
    const float* p = in + ((size_t)c * H + 2 * y) * W + 2 * x;
    out[idx] = fmaxf(fmaxf(p[0], p[1]), fmaxf(p[W], p[W + 1]));
}

// ======================= transpose (R x C) -> (C x R) ========================
__global__ void transpose_kernel(const float* __restrict__ in, float* __restrict__ out,
                                 int R, int C)
{
    __shared__ float tile[32][33];
    int bx = blockIdx.x * 32, by = blockIdx.y * 32;
    int x = bx + threadIdx.x;
    for (int i = threadIdx.y; i < 32; i += 8) {
        int y = by + i;
        tile[i][threadIdx.x] = in[(size_t)y * C + x];
    }
    __syncthreads();
    for (int i = threadIdx.y; i < 32; i += 8) {
        out[(size_t)(bx + i) * R + (by + threadIdx.x)] = tile[threadIdx.x][i];
    }
}

// ======================= LayerNorm over dim 256 ==============================
__global__ void ln_kernel(const float* __restrict__ in, float* __restrict__ out,
                          const float* __restrict__ g, const float* __restrict__ b)
{
    int row = blockIdx.x, tid = threadIdx.x;
    __shared__ float sm[8];
    float v = in[(size_t)row * 256 + tid];
    float s = v;
    #pragma unroll
    for (int o = 16; o; o >>= 1) s += __shfl_xor_sync(0xffffffffu, s, o);
    if ((tid & 31) == 0) sm[tid >> 5] = s;
    __syncthreads();
    float tot = 0.f;
    #pragma unroll
    for (int i = 0; i < 8; i++) tot += sm[i];
    float mean = tot * (1.f / 256.f);
    float c = v - mean;
    __syncthreads();
    float s2 = c * c;
    #pragma unroll
    for (int o = 16; o; o >>= 1) s2 += __shfl_xor_sync(0xffffffffu, s2, o);
    if ((tid & 31) == 0) sm[tid >> 5] = s2;
    __syncthreads();
    float tot2 = 0.f;
    #pragma unroll
    for (int i = 0; i < 8; i++) tot2 += sm[i];
    float var = tot2 * (1.f / 256.f);
    out[(size_t)row * 256 + tid] = c / sqrtf(var + 1e-5f) * g[tid] + b[tid];
}

// ======================= SGEMM 128x64 tile, 8x4 micro, FFMA2, dual-output ====
__global__ void sgemm_kernel(const float* __restrict__ A,
                             const float* __restrict__ B0, const float* __restrict__ bias0,
                             const float* __restrict__ res0, float* __restrict__ C0,
                             const float* __restrict__ B1, const float* __restrict__ bias1,
                             const float* __restrict__ res1, float* __restrict__ C1,
                             int M, int N, int K, int act)
{
    const float* __restrict__ B    = (blockIdx.z == 0) ? B0 : B1;
    const float* __restrict__ bias = (blockIdx.z == 0) ? bias0 : bias1;
    const float* __restrict__ res  = (blockIdx.z == 0) ? res0 : res1;
    float* __restrict__ C          = (blockIdx.z == 0) ? C0 : C1;
    __shared__ float As[2][16][132];
    __shared__ float Bs[2][16][64];
    const int tid = threadIdx.x;
    const int m0 = blockIdx.y * 128, n0 = blockIdx.x * 64;
    const int la_m = tid >> 1, la_k = (tid & 1) * 8;
    const int lb_k = tid >> 4, lb_n = (tid & 15) * 4;
    const int tx = tid & 15, ty = tid >> 4;
    const float* Ap = A + (size_t)(m0 + la_m) * K + la_k;
    const float* Bp = B + (size_t)lb_k * N + n0 + lb_n;
    unsigned long long acc2[4][4];
    #pragma unroll
    for (int i = 0; i < 4; i++)
        #pragma unroll
        for (int j = 0; j < 4; j++) acc2[i][j] = 0ull;
    float4 pa0 = *(const float4*)Ap;
    float4 pa1 = *(const float4*)(Ap + 4);
    float4 pb  = *(const float4*)Bp;
    As[0][la_k+0][la_m]=pa0.x; As[0][la_k+1][la_m]=pa0.y;
    As[0][la_k+2][la_m]=pa0.z; As[0][la_k+3][la_m]=pa0.w;
    As[0][la_k+4][la_m]=pa1.x; As[0][la_k+5][la_m]=pa1.y;
    As[0][la_k+6][la_m]=pa1.z; As[0][la_k+7][la_m]=pa1.w;
    *(float4*)&Bs[0][lb_k][lb_n] = pb;
    __syncthreads();
    const int nk = K >> 4;
    int buf = 0;
    for (int kc = 0; kc < nk; kc++) {
        if (kc + 1 < nk) {
            pa0 = *(const float4*)(Ap + (kc + 1) * 16);
            pa1 = *(const float4*)(Ap + (kc + 1) * 16 + 4);
            pb  = *(const float4*)(Bp + (size_t)(kc + 1) * 16 * N);
        }
        #pragma unroll
        for (int k = 0; k < 16; k++) {
            float4 a0 = *(const float4*)&As[buf][k][ty * 8];
            float4 a1 = *(const float4*)&As[buf][k][ty * 8 + 4];
            float4 b0 = *(const float4*)&Bs[buf][k][tx * 4];
            unsigned long long ap[4] = { pack2(a0.x, a0.y), pack2(a0.z, a0.w),
                                         pack2(a1.x, a1.y), pack2(a1.z, a1.w) };
            unsigned long long bd[4] = { dup2(b0.x), dup2(b0.y), dup2(b0.z), dup2(b0.w) };
            #pragma unroll
            for (int i = 0; i < 4; i++)
                #pragma unroll
                for (int j = 0; j < 4; j++)
                    fma2(acc2[i][j], ap[i], bd[j]);
        }
        if (kc + 1 < nk) {
            buf ^= 1;
            As[buf][la_k+0][la_m]=pa0.x; As[buf][la_k+1][la_m]=pa0.y;
            As[buf][la_k+2][la_m]=pa0.z; As[buf][la_k+3][la_m]=pa0.w;
            As[buf][la_k+4][la_m]=pa1.x; As[buf][la_k+5][la_m]=pa1.y;
            As[buf][la_k+6][la_m]=pa1.z; As[buf][la_k+7][la_m]=pa1.w;
            *(float4*)&Bs[buf][lb_k][lb_n] = pb;
            __syncthreads();
        }
    }
    float4 bi = *(const float4*)(bias + n0 + tx * 4);
    #pragma unroll
    for (int ip = 0; ip < 4; ip++) {
        float2 e0 = unpack2(acc2[ip][0]), e1 = unpack2(acc2[ip][1]);
        float2 e2 = unpack2(acc2[ip][2]), e3 = unpack2(acc2[ip][3]);
        float rows[2][4] = {{e0.x, e1.x, e2.x, e3.x}, {e0.y, e1.y, e2.y, e3.y}};
        #pragma unroll
        for (int s = 0; s < 2; s++) {
            int m = m0 + ty * 8 + ip * 2 + s;
            float4 r;
            r.x = rows[s][0] + bi.x; r.y = rows[s][1] + bi.y;
            r.z = rows[s][2] + bi.z; r.w = rows[s][3] + bi.w;
            if (act == 1) {
                float xs[4] = {r.x, r.y, r.z, r.w};
                #pragma unroll
                for (int j = 0; j < 4; j++) {
                    float x = xs[j];
                    xs[j] = 0.5f * x * (1.f + tanhf(0.7978845608f * (x + 0.044715f * x * x * x)));
                }
                r.x = xs[0]; r.y = xs[1]; r.z = xs[2]; r.w = xs[3];
            }
            if (res) {
                float4 rr = *(const float4*)(res + (size_t)m * N + n0 + tx * 4);
                r.x += rr.x; r.y += rr.y; r.z += rr.z; r.w += rr.w;
            }
            *(float4*)(C + (size_t)m * N + n0 + tx * 4) = r;
        }
    }
}

// ======================= SGEMM 128x128 tile, 8x8 micro, FFMA2 (for FF1) =====
__global__ void sgemm128_kernel(const float* __restrict__ A, const float* __restrict__ B,
                                const float* __restrict__ bias,
                                float* __restrict__ C, int M, int N, int K, int act)
{
    __shared__ float As[2][16][132];
    __shared__ float Bs[2][16][132];
    const int tid = threadIdx.x;
    const int m0 = blockIdx.y * 128, n0 = blockIdx.x * 128;
    const int la_m = tid >> 1, la_k = (tid & 1) * 8;
    const int lb_k = tid >> 4, lb_n = (tid & 15) * 8;
    const int tx = tid & 15, ty = tid >> 4;
    const float* Ap = A + (size_t)(m0 + la_m) * K + la_k;
    const float* Bp = B + (size_t)lb_k * N + n0 + lb_n;
    unsigned long long acc2[4][8];
    #pragma unroll
    for (int i = 0; i < 4; i++)
        #pragma unroll
        for (int j = 0; j < 8; j++) acc2[i][j] = 0ull;
    float4 pa0 = *(const float4*)Ap;
    float4 pa1 = *(const float4*)(Ap + 4);
    float4 pb0 = *(const float4*)Bp;
    float4 pb1 = *(const float4*)(Bp + 4);
    As[0][la_k+0][la_m]=pa0.x; As[0][la_k+1][la_m]=pa0.y;
    As[0][la_k+2][la_m]=pa0.z; As[0][la_k+3][la_m]=pa0.w;
    As[0][la_k+4][la_m]=pa1.x; As[0][la_k+5][la_m]=pa1.y;
    As[0][la_k+6][la_m]=pa1.z; As[0][la_k+7][la_m]=pa1.w;
    *(float4*)&Bs[0][lb_k][lb_n]     = pb0;
    *(float4*)&Bs[0][lb_k][lb_n + 4] = pb1;
    __syncthreads();
    const int nk = K >> 4;
    int buf = 0;
    for (int kc = 0; kc < nk; kc++) {
        if (kc + 1 < nk) {
            pa0 = *(const float4*)(Ap + (kc + 1) * 16);
            pa1 = *(const float4*)(Ap + (kc + 1) * 16 + 4);
            pb0 = *(const float4*)(Bp + (size_t)(kc + 1) * 16 * N);
            pb1 = *(const float4*)(Bp + (size_t)(kc + 1) * 16 * N + 4);
        }
        #pragma unroll
        for (int k = 0; k < 16; k++) {
            float4 a0 = *(const float4*)&As[buf][k][ty * 8];
            float4 a1 = *(const float4*)&As[buf][k][ty * 8 + 4];
            float4 b0 = *(const float4*)&Bs[buf][k][tx * 8];
            float4 b1 = *(const float4*)&Bs[buf][k][tx * 8 + 4];
            unsigned long long ap[4] = { pack2(a0.x, a0.y), pack2(a0.z, a0.w),
                                         pack2(a1.x, a1.y), pack2(a1.z, a1.w) };
            unsigned long long bd[8] = { dup2(b0.x), dup2(b0.y), dup2(b0.z), dup2(b0.w),
                                         dup2(b1.x), dup2(b1.y), dup2(b1.z), dup2(b1.w) };
            #pragma unroll
            for (int i = 0; i < 4; i++)
                #pragma unroll
                for (int j = 0; j < 8; j++)
                    fma2(acc2[i][j], ap[i], bd[j]);
        }
        if (kc + 1 < nk) {
            buf ^= 1;
            As[buf][la_k+0][la_m]=pa0.x; As[buf][la_k+1][la_m]=pa0.y;
            As[buf][la_k+2][la_m]=pa0.z; As[buf][la_k+3][la_m]=pa0.w;
            As[buf][la_k+4][la_m]=pa1.x; As[buf][la_k+5][la_m]=pa1.y;
            As[buf][la_k+6][la_m]=pa1.z; As[buf][la_k+7][la_m]=pa1.w;
            *(float4*)&Bs[buf][lb_k][lb_n]     = pb0;
            *(float4*)&Bs[buf][lb_k][lb_n + 4] = pb1;
            __syncthreads();
        }
    }
    float4 bi0 = *(const float4*)(bias + n0 + tx * 8);
    float4 bi1 = *(const float4*)(bias + n0 + tx * 8 + 4);
    float bb[8] = {bi0.x, bi0.y, bi0.z, bi0.w, bi1.x, bi1.y, bi1.z, bi1.w};
    #pragma unroll
    for (int ip = 0; ip < 4; ip++) {
        float2 e[8];
        #pragma unroll
        for (int j = 0; j < 8; j++) e[j] = unpack2(acc2[ip][j]);
        #pragma unroll
        for (int s = 0; s < 2; s++) {
            int m = m0 + ty * 8 + ip * 2 + s;
            float xs[8];
            #pragma unroll
            for (int j = 0; j < 8; j++) {
                float x = ((s == 0) ? e[j].x : e[j].y) + bb[j];
                if (act == 1)
                    x = 0.5f * x * (1.f + tanhf(0.7978845608f * (x + 0.044715f * x * x * x)));
                xs[j] = x;
            }
            *(float4*)(C + (size_t)m * N + n0 + tx * 8)     = make_float4(xs[0], xs[1], xs[2], xs[3]);
            *(float4*)(C + (size_t)m * N + n0 + tx * 8 + 4) = make_float4(xs[4], xs[5], xs[6], xs[7]);
        }
    }
}

// ======================= LSH bucketing + histogram ===========================
__global__ void bucket_kernel(const float* __restrict__ qk, const float* __restrict__ rot,
                              float* __restrict__ kinv, int* __restrict__ bucket,
                              int* __restrict__ hist)
{
    int n = blockIdx.x, h = blockIdx.y, lane = threadIdx.x;
    __shared__ float q[64];
    float q0 = qk[(size_t)n * 256 + h * 64 + lane];
    float q1 = qk[(size_t)n * 256 + h * 64 + 32 + lane];
    q[lane] = q0; q[lane + 32] = q1;
    __syncwarp();
    float ss = q0 * q0 + q1 * q1;
    #pragma unroll
    for (int o = 16; o; o >>= 1) ss += __shfl_xor_sync(0xffffffffu, ss, o);
    if (lane == 0) kinv[h * 4096 + n] = 1.f / (sqrtf(ss) + 1e-6f);

    float acc = 0.f;
    const float* rp = rot + (size_t)h * 64 * 32 + lane;
    #pragma unroll 8
    for (int d = 0; d < 64; d++) acc = fmaf(q[d], rp[(size_t)d * 32], acc);
    float bv = acc; int bi = lane;
    if (-acc > bv) { bv = -acc; bi = lane + 32; }
    #pragma unroll
    for (int o = 16; o; o >>= 1) {
        float ov = __shfl_xor_sync(0xffffffffu, bv, o);
        int oi = __shfl_xor_sync(0xffffffffu, bi, o);
        if (ov > bv || (ov == bv && oi < bi)) { bv = ov; bi = oi; }
    }
    if (lane == 0) {
        bucket[h * 4096 + n] = bi;
        atomicAdd(&hist[(h << 6) + bi], 1);
    }
}

// stable counting-sort scatter (prefix computed in-block from hist)
__global__ void scatter_kernel(const int* __restrict__ bucket, const int* __restrict__ hist,
                               int* __restrict__ perm)
{
    int b = blockIdx.x, h = blockIdx.y, lane = threadIdx.x;
    int base = 0;
    for (int i = lane; i < b; i += 32) base += hist[h * 64 + i];
    #pragma unroll
    for (int o = 16; o; o >>= 1) base += __shfl_xor_sync(0xffffffffu, base, o);
    const int* bk = bucket + h * 4096;
    for (int n0 = 0; n0 < 4096; n0 += 32) {
        int v = bk[n0 + lane];
        unsigned m = __ballot_sync(0xffffffffu, v == b);
        if (v == b)
            perm[h * 4096 + base + __popc(m & ((1u << lane) - 1u))] = n0 + lane;
        base += __popc(m);
    }
}

// ======================= dots + softmax fused (64 q x 128 k, d=64) ===========
__global__ void dots_kernel(const float* __restrict__ qk, const float* __restrict__ kinv,
                            const int* __restrict__ perm, float* __restrict__ dots)
{
    int c = blockIdx.x, h = blockIdx.y, tid = threadIdx.x;
    __shared__ float qs[16][68];
    __shared__ float ks[16][132];
    __shared__ int tok[128];
    __shared__ float kiv[128];
    int cprev = (c + 63) & 63;
    if (tid < 128) {
        int p = (tid < 64) ? c * 64 + tid : cprev * 64 + (tid - 64);
        int t = perm[h * 4096 + p];
        tok[tid] = t;
        kiv[tid] = kinv[h * 4096 + t];
    }
    __syncthreads();
    const int tx = tid & 15, ty = tid >> 4;
    float acc[4][8] = {};
    for (int d0 = 0; d0 < 64; d0 += 16) {
        {
            int q = tid & 63, dsub = tid >> 6;
            float4 v4 = *(const float4*)(qk + (size_t)tok[q] * 256 + h * 64 + d0 + dsub * 4);
            qs[dsub*4+0][q] = v4.x; qs[dsub*4+1][q] = v4.y;
            qs[dsub*4+2][q] = v4.z; qs[dsub*4+3][q] = v4.w;
        }
        #pragma unroll
        for (int r = 0; r < 2; r++) {
            int idx = tid + r * 256;
            int j = idx & 127, dsub = idx >> 7;
            float sc = kiv[j];
            float4 v4 = *(const float4*)(qk + (size_t)tok[j] * 256 + h * 64 + d0 + dsub * 4);
            ks[dsub*4+0][j] = v4.x * sc; ks[dsub*4+1][j] = v4.y * sc;
            ks[dsub*4+2][j] = v4.z * sc; ks[dsub*4+3][j] = v4.w * sc;
        }
        __syncthreads();
        #pragma unroll
        for (int d = 0; d < 16; d++) {
            float4 q0 = *(const float4*)&qs[d][ty * 4];
            float4 k0 = *(const float4*)&ks[d][tx * 8];
            float4 k1 = *(const float4*)&ks[d][tx * 8 + 4];
            float qq[4] = {q0.x, q0.y, q0.z, q0.w};
            float kk[8] = {k0.x, k0.y, k0.z, k0.w, k1.x, k1.y, k1.z, k1.w};
            #pragma unroll
            for (int i = 0; i < 4; i++)
                #pragma unroll
                for (int j = 0; j < 8; j++)
                    acc[i][j] = fmaf(qq[i], kk[j], acc[i][j]);
        }
        __syncthreads();
    }
    float* outp = dots + (((size_t)h * 64 + c) * 64) * 128;
    #pragma unroll
    for (int i = 0; i < 4; i++) {
        int ii = ty * 4 + i;
        int ti = tok[ii];
        float v[8];
        float mx = -3.402823e38f;
        #pragma unroll
        for (int j = 0; j < 8; j++) {
            float x = acc[i][j] * 0.125f;
            if (ti == tok[tx * 8 + j]) x = -1e5f;
            v[j] = x;
            mx = fmaxf(mx, x);
        }
        #pragma unroll
        for (int o = 1; o < 16; o <<= 1) mx = fmaxf(mx, __shfl_xor_sync(0xffffffffu, mx, o));
        float s = 0.f;
        #pragma unroll
        for (int j = 0; j < 8; j++) { v[j] = expf(v[j] - mx); s += v[j]; }
        #pragma unroll
        for (int o = 1; o < 16; o <<= 1) s += __shfl_xor_sync(0xffffffffu, s, o);
        float inv = 1.f / s;
        float4 o0 = make_float4(v[0]*inv, v[1]*inv, v[2]*inv, v[3]*inv);
        float4 o1 = make_float4(v[4]*inv, v[5]*inv, v[6]*inv, v[7]*inv);
        *(float4*)(outp + ii * 128 + tx * 8)     = o0;
        *(float4*)(outp + ii * 128 + tx * 8 + 4) = o1;
    }
}

// ======================= attn @ V (64x128 @ 128x64), scatter unsorted ========
__global__ void av_kernel(const float* __restrict__ v, const int* __restrict__ perm,
                          const float* __restrict__ dots, float* __restrict__ out)
{
    int c = blockIdx.x, h = blockIdx.y, tid = threadIdx.x;
    __shared__ float As[16][68];
    __shared__ float Bs[16][68];
    __shared__ int tok[128];
    int cprev = (c + 63) & 63;
    if (tid < 128) {
        int p = (tid < 64) ? c * 64 + tid : cprev * 64 + (tid - 64);
        tok[tid] = perm[h * 4096 + p];
    }
    __syncthreads();
    const int tx = tid & 7, ty = tid >> 3;
    float acc[2][8] = {};
    const float* ap = dots + (((size_t)h * 64 + c) * 64) * 128;
    for (int j0 = 0; j0 < 128; j0 += 16) {
        {
            int q = tid & 63, jsub = tid >> 6;
            float4 a4 = *(const float4*)(ap + q * 128 + j0 + jsub * 4);
            As[jsub*4+0][q] = a4.x; As[jsub*4+1][q] = a4.y;
            As[jsub*4+2][q] = a4.z; As[jsub*4+3][q] = a4.w;
        }
        {
            int k = tid >> 4, dsub = tid & 15;
            float4 v4 = *(const float4*)(v + (size_t)tok[j0 + k] * 256 + h * 64 + dsub * 4);
            *(float4*)&Bs[k][dsub * 4] = v4;
        }
        __syncthreads();
        #pragma unroll
        for (int k = 0; k < 16; k++) {
            float a0 = As[k][ty * 2], a1 = As[k][ty * 2 + 1];
            float4 b0 = *(const float4*)&Bs[k][tx * 8];
            float4 b1 = *(const float4*)&Bs[k][tx * 8 + 4];
            float bb[8] = {b0.x, b0.y, b0.z, b0.w, b1.x, b1.y, b1.z, b1.w};
            #pragma unroll
            for (int j = 0; j < 8; j++) {
                acc[0][j] = fmaf(a0, bb[j], acc[0][j]);
                acc[1][j] = fmaf(a1, bb[j], acc[1][j]);
            }
        }
        __syncthreads();
    }
    #pragma unroll
    for (int r = 0; r < 2; r++) {
        int ii = ty * 2 + r;
        float* op = out + (size_t)tok[ii] * 256 + h * 64 + tx * 8;
        *(float4*)op       = make_float4(acc[r][0], acc[r][1], acc[r][2], acc[r][3]);
        *(float4*)(op + 4) = make_float4(acc[r][4], acc[r][5], acc[r][6], acc[r][7]);
    }
}

// ======================= host launch ========================================
extern "C" void kernel_launch(void* const* d_in, const int* in_sizes, int n_in,
                              void* d_out, int out_size)
{
    (void)in_sizes; (void)n_in; (void)out_size;
    const float* burst   = (const float*)d_in[0];
    const float* conv1_w = (const float*)d_in[1];
    const float* conv1_b = (const float*)d_in[2];
    const float* conv2_w = (const float*)d_in[3];
    const float* conv2_b = (const float*)d_in[4];
    const float* conv3_w = (const float*)d_in[5];
    const float* conv3_b = (const float*)d_in[6];
    const float* ln1_g   = (const float*)d_in[7];
    const float* ln1_b   = (const float*)d_in[8];
    const float* Wqk     = (const float*)d_in[9];
    const float* bqk     = (const float*)d_in[10];
    const float* Wv      = (const float*)d_in[11];
    const float* bv      = (const float*)d_in[12];
    const float* Wo      = (const float*)d_in[13];
    const float* bo      = (const float*)d_in[14];
    const float* rot     = (const float*)d_in[15];
    const float* ln2_g   = (const float*)d_in[16];
    const float* ln2_b   = (const float*)d_in[17];
    const float* Wff1    = (const float*)d_in[18];
    const float* bff1    = (const float*)d_in[19];
    const float* Wff2    = (const float*)d_in[20];
    const float* bff2    = (const float*)d_in[21];
    const float* up1_w   = (const float*)d_in[22];
    const float* up1_b   = (const float*)d_in[23];
    const float* dec1_w  = (const float*)d_in[24];
    const float* dec1_b  = (const float*)d_in[25];
    const float* up2_w   = (const float*)d_in[26];
    const float* up2_b   = (const float*)d_in[27];
    const float* dec2_w  = (const float*)d_in[28];
    const float* dec2_b  = (const float*)d_in[29];
    const float* out_w   = (const float*)d_in[30];
    const float* out_b   = (const float*)d_in[31];

    float* AR = nullptr; int* IB = nullptr;
    cudaGetSymbolAddress((void**)&AR, g_arena);
    cudaGetSymbolAddress((void**)&IB, g_ibuf);

    float* E1  = AR + OFF_E1;   float* P1  = AR + OFF_P1;
    float* E2  = AR + OFF_E2;   float* P2  = AR + OFF_P2;
    float* SEQ = AR + OFF_SEQ;  float* LNB = AR + OFF_LN;
    float* QK  = AR + OFF_QK;   float* V   = AR + OFF_V;
    float* KINV= AR + OFF_KINV; float* DOTS= AR + OFF_DOTS;
    float* AO  = AR + OFF_AO;   float* FFH = AR + OFF_FFH;
    float* BM  = AR + OFF_BM;   float* UP1 = AR + OFF_UP1;
    float* D1  = AR + OFF_D1;   float* UP2 = AR + OFF_UP2;
    float* D2  = AR + OFF_D2;
    int* BKT = IB + IOFF_BUCKET; int* PRM = IB + IOFF_PERM;
    int* HST = IB + IOFF_HIST;

    dim3 b16(16, 16);

    // -------- encoder (implicit-GEMM convs) --------
    convg_kernel<<<dim3(512, 1), 256>>>(burst, 3, nullptr, 0, conv1_w, conv1_b, E1, 256, 256, 8, 64, 0);
    maxpool_kernel<<<(64 * 128 * 128 + 255) / 256, 256>>>(E1, P1, 64, 256, 256);
    convg_kernel<<<dim3(128, 2), 256>>>(P1, 64, nullptr, 0, conv2_w, conv2_b, E2, 128, 128, 7, 128, 0);
    maxpool_kernel<<<(128 * 64 * 64 + 255) / 256, 256>>>(E2, P2, 128, 128, 128);
    convg_kernel<<<dim3(32, 4), 256>>>(P2, 128, nullptr, 0, conv3_w, conv3_b, BM, 64, 64, 6, 256, 0);
    transpose_kernel<<<dim3(128, 8), dim3(32, 8)>>>(BM, SEQ, 256, 4096);

    // -------- reformer (4 layers) --------
    for (int l = 0; l < 4; l++) {
        ln_kernel<<<4096, 256>>>(SEQ, LNB, ln1_g + l * 256, ln1_b + l * 256);
        sgemm_kernel<<<dim3(4, 32, 2), 256>>>(LNB,
            Wqk + (size_t)l * 65536, bqk + l * 256, nullptr, QK,
            Wv  + (size_t)l * 65536, bv  + l * 256, nullptr, V,
            4096, 256, 256, 0);
        cudaMemsetAsync(HST, 0, 256 * sizeof(int));
        bucket_kernel<<<dim3(4096, 4), 32>>>(QK, rot + (size_t)l * 4 * 64 * 32, KINV, BKT, HST);
        scatter_kernel<<<dim3(64, 4), 32>>>(BKT, HST, PRM);
        dots_kernel<<<dim3(64, 4), 256>>>(QK, KINV, PRM, DOTS);
        av_kernel<<<dim3(64, 4), 256>>>(V, PRM, DOTS, AO);
        sgemm_kernel<<<dim3(4, 32, 1), 256>>>(AO,
            Wo + (size_t)l * 65536, bo + l * 256, SEQ, SEQ,
            nullptr, nullptr, nullptr, nullptr,
            4096, 256, 256, 0);
        ln_kernel<<<4096, 256>>>(SEQ, LNB, ln2_g + l * 256, ln2_b + l * 256);
        sgemm128_kernel<<<dim3(8, 32), 256>>>(LNB, Wff1 + (size_t)l * 262144, bff1 + l * 1024, FFH, 4096, 1024, 256, 1);
        sgemm_kernel<<<dim3(4, 32, 1), 256>>>(FFH,
            Wff2 + (size_t)l * 262144, bff2 + l * 256, SEQ, SEQ,
            nullptr, nullptr, nullptr, nullptr,
            4096, 256, 1024, 0);
    }

    // -------- decoder (implicit-GEMM convT + convs) --------
    transpose_kernel<<<dim3(8, 128), dim3(32, 8)>>>(SEQ, BM, 4096, 256);
    convtg_kernel<<<dim3(32, 2, 4), 256>>>(BM, up1_w, up1_b, UP1, 64, 64, 6, 256, 128);
    convg_kernel<<<dim3(128, 2), 256>>>(UP1, 128, E2, 128, dec1_w, dec1_b, D1, 128, 128, 7, 128, 0);
    convtg_kernel<<<dim3(128, 1, 4), 256>>>(D1, up2_w, up2_b, UP2, 128, 128, 7, 128, 64);
    convg_kernel<<<dim3(512, 1), 256>>>(UP2, 64, E1, 64, dec2_w, dec2_b, D2, 256, 256, 8, 64, 0);
    conv3x3_kernel<<<dim3(8, 8, 1), b16>>>(D2, 64, nullptr, 0, out_w, out_b, (float*)d_out, 256, 256, 3, 2);
}